// round 2
// baseline (speedup 1.0000x reference)
#include <cuda_runtime.h>
#include <math.h>

#define Bb 32
#define Nn 512
#define Mm 512
#define EPSV 0.05f
#define NITERS 50
#define NEGC (-1e9f)

// Scratch (device globals: allocation-free per harness rules)
__device__ float g_K [(size_t)Bb * Nn * Mm];   // logK row-major   [b][i][j]
__device__ float g_KT[(size_t)Bb * Mm * Nn];   // logK transposed  [b][j][i]
__device__ float g_loga[Bb * Nn];
__device__ float g_logb[Bb * Mm];
__device__ float g_logu[Bb * Nn];
__device__ float g_logv[Bb * Mm];

// ---------------------------------------------------------------------------
// prep: per-batch masses, log-weights, logv init, huber term into out[b]
// grid = B, block = 512
__global__ void prep_kernel(const float* __restrict__ a_mask,
                            const float* __restrict__ pc_a,
                            const float* __restrict__ b_mask,
                            const float* __restrict__ pc_b,
                            float* __restrict__ out)
{
    int b = blockIdx.x, t = threadIdx.x;
    float apt = a_mask[b * Nn + t] * pc_a[(b * Nn + t) * 3 + 2];
    float bpt = b_mask[b * Mm + t] * pc_b[(b * Mm + t) * 3 + 2];

    __shared__ float ra[512], rb[512];
    ra[t] = apt; rb[t] = bpt;
    __syncthreads();
    for (int o = 256; o; o >>= 1) {
        if (t < o) { ra[t] += ra[t + o]; rb[t] += rb[t + o]; }
        __syncthreads();
    }
    float sa = ra[0], sb = rb[0];

    g_loga[b * Nn + t] = (apt > 0.f) ? logf(apt / sa) : NEGC;
    g_logb[b * Mm + t] = (bpt > 0.f) ? logf(bpt / sb) : NEGC;
    g_logv[b * Mm + t] = 0.f;   // reference starts logv = 0

    if (t == 0) {
        float e = sa - sb;
        float ae = fabsf(e);
        out[b] = (ae <= 1.f) ? 0.5f * e * e : (ae - 0.5f);
    }
}

// ---------------------------------------------------------------------------
// build logK and logK^T.  grid = (M/32, N/32, B), block = (32, 32)
__global__ void computeK_kernel(const float* __restrict__ a_mask,
                                const float* __restrict__ pc_a,
                                const float* __restrict__ b_mask,
                                const float* __restrict__ pc_b)
{
    int b  = blockIdx.z;
    int i0 = blockIdx.y * 32, j0 = blockIdx.x * 32;
    int tx = threadIdx.x, ty = threadIdx.y;

    __shared__ float ax[32], ay[32], av[32];
    __shared__ float bx[32], by[32], bv[32];
    __shared__ float tile[32][33];

    if (ty == 0) {
        int i = i0 + tx; int base = (b * Nn + i) * 3;
        ax[tx] = pc_a[base + 0];
        ay[tx] = pc_a[base + 1];
        av[tx] = (a_mask[b * Nn + i] * pc_a[base + 2] > 0.f) ? 1.f : 0.f;
    } else if (ty == 1) {
        int j = j0 + tx; int base = (b * Mm + j) * 3;
        bx[tx] = pc_b[base + 0];
        by[tx] = pc_b[base + 1];
        bv[tx] = (b_mask[b * Mm + j] * pc_b[base + 2] > 0.f) ? 1.f : 0.f;
    }
    __syncthreads();

    float dx = ax[ty] - bx[tx];
    float dy = ay[ty] - by[tx];
    float d  = sqrtf(dx * dx + dy * dy + 1e-12f);
    float val = (av[ty] * bv[tx] > 0.f) ? (-d * (1.f / EPSV)) : 0.f;

    g_K[((size_t)(b * Nn + (i0 + ty))) * Mm + (j0 + tx)] = val;
    tile[ty][tx] = val;
    __syncthreads();
    g_KT[((size_t)(b * Mm + (j0 + ty))) * Nn + (i0 + tx)] = tile[tx][ty];
}

// ---------------------------------------------------------------------------
// one lse half-pass: dst[row] = w[row] - logsumexp_j( K[row][j] + src[j] )
// warp-per-row, row (512 fp32) cached in 16 regs/lane, 1 exp per element.
// grid = B*512/8, block = 256 (8 warps)
template <bool UPASS>
__global__ void lse_kernel()
{
    const float* __restrict__ K   = UPASS ? g_K    : g_KT;
    const float* __restrict__ src = UPASS ? g_logv : g_logu;
    const float* __restrict__ w   = UPASS ? g_loga : g_logb;
    float*       __restrict__ dst = UPASS ? g_logu : g_logv;

    __shared__ float sv[512];
    int b    = blockIdx.x >> 6;          // 64 blocks per batch
    int row0 = (blockIdx.x & 63) * 8;

    for (int t = threadIdx.x; t < 512; t += 256)
        sv[t] = src[b * 512 + t];
    __syncthreads();

    int warp = threadIdx.x >> 5, lane = threadIdx.x & 31;
    int i = row0 + warp;
    const float* Kr = K + ((size_t)(b * 512 + i)) * 512;

    float x[16];
    float m = -3.4e38f;
#pragma unroll
    for (int k = 0; k < 16; k++) {
        x[k] = Kr[lane + 32 * k] + sv[lane + 32 * k];
        m = fmaxf(m, x[k]);
    }
#pragma unroll
    for (int o = 16; o; o >>= 1) m = fmaxf(m, __shfl_xor_sync(0xFFFFFFFFu, m, o));

    float s = 0.f;
#pragma unroll
    for (int k = 0; k < 16; k++) s += __expf(x[k] - m);
#pragma unroll
    for (int o = 16; o; o >>= 1) s += __shfl_xor_sync(0xFFFFFFFFu, s, o);

    if (lane == 0)
        dst[b * 512 + i] = w[b * 512 + i] - (m + __logf(s));
}

// ---------------------------------------------------------------------------
// final: out[b] += sum_ij dist^2 * exp(logu + logK + logv), dist = -EPS*logK
// grid = B, block = 512 (thread t owns column t; deterministic reduction)
__global__ void final_kernel(float* __restrict__ out)
{
    int b = blockIdx.x, t = threadIdx.x;
    __shared__ float sv[512];
    __shared__ float red[512];
    sv[t] = g_logv[b * 512 + t];
    __syncthreads();

    const float* Kb = g_K + (size_t)b * 512 * 512;
    float acc = 0.f;
    for (int i = 0; i < 512; i++) {
        float lu = g_logu[b * 512 + i];       // uniform -> broadcast load
        float k  = Kb[(size_t)i * 512 + t];
        acc += k * k * __expf(lu + k + sv[t]);
    }

    red[t] = acc;
    __syncthreads();
    for (int o = 256; o; o >>= 1) {
        if (t < o) red[t] += red[t + o];
        __syncthreads();
    }
    if (t == 0) out[b] += (EPSV * EPSV) * red[0];
}

// ---------------------------------------------------------------------------
extern "C" void kernel_launch(void* const* d_in, const int* in_sizes, int n_in,
                              void* d_out, int out_size)
{
    const float* a_mask = (const float*)d_in[0];
    const float* pc_a   = (const float*)d_in[1];
    const float* b_mask = (const float*)d_in[2];
    const float* pc_b   = (const float*)d_in[3];
    float* out = (float*)d_out;

    prep_kernel<<<Bb, 512>>>(a_mask, pc_a, b_mask, pc_b, out);
    computeK_kernel<<<dim3(Mm / 32, Nn / 32, Bb), dim3(32, 32)>>>(a_mask, pc_a, b_mask, pc_b);

    for (int it = 0; it < NITERS; ++it) {
        lse_kernel<true ><<<Bb * Nn / 8, 256>>>();   // logu update (reads K,  logv)
        lse_kernel<false><<<Bb * Mm / 8, 256>>>();   // logv update (reads KT, logu)
    }

    final_kernel<<<Bb, 512>>>(out);
}